// round 11
// baseline (speedup 1.0000x reference)
#include <cuda_runtime.h>
#include <cuda_fp16.h>
#include <cstdint>

// Problem constants: N=100000, S=8, B=4, F=128, O=64, E=3.2M
#define MAXN 100000
#define MAXE 3300000
#define FDIM 128
#define ODIM 64
#define NBAS 4
#define NREL 8

// Scratch (__device__ globals; no runtime alloc allowed)
__device__ __half g_FWh[(size_t)NREL * MAXN * ODIM];  // [8, N, 64] fp16 (102.4 MB)
__device__ __half g_Wh[NREL * ODIM * FDIM];           // [8][n=64][k=128] fp16
__device__ int    g_cnt[MAXN];
__device__ int    g_off[MAXN + 1];
__device__ int    g_pos[MAXN];
__device__ uint2  g_pairs[MAXE];                      // (col, val-bits), row-sorted

// ---------------------------------------------------------------------------
__device__ __forceinline__ void mma_f16(float* d, uint32_t a0, uint32_t a1, uint32_t a2,
                                        uint32_t a3, uint32_t b0, uint32_t b1) {
    asm volatile(
        "mma.sync.aligned.m16n8k16.row.col.f32.f16.f16.f32 "
        "{%0,%1,%2,%3}, {%4,%5,%6,%7}, {%8,%9}, {%0,%1,%2,%3};"
        : "+f"(d[0]), "+f"(d[1]), "+f"(d[2]), "+f"(d[3])
        : "r"(a0), "r"(a1), "r"(a2), "r"(a3), "r"(b0), "r"(b1));
}

// ---------------------------------------------------------------------------
// Kernel 0: W[s][n][k] = fp16( sum_b comp[s,b] * Bases[b][k][n] )
// ---------------------------------------------------------------------------
__global__ void wcomb_kernel(const float* __restrict__ bases, const float* __restrict__ comp) {
    int idx = blockIdx.x * blockDim.x + threadIdx.x;
    if (idx >= NREL * FDIM * ODIM) return;
    int s = idx >> 13;
    int r = idx & 8191;
    int n = r >> 7;
    int k = r & 127;
    float acc = 0.f;
    #pragma unroll
    for (int b = 0; b < NBAS; b++)
        acc += __ldg(comp + s * NBAS + b) * __ldg(bases + b * FDIM * ODIM + k * ODIM + n);
    g_Wh[idx] = __float2half_rn(acc);
}

// ---------------------------------------------------------------------------
// Kernel 1: FW[s] = X @ W[s]^T via fp16 mma; staged epilogue; W reg-prefetch.
// (round-10 version, best known)
// ---------------------------------------------------------------------------
#define XS_STRIDE 136
#define WS_STRIDE 136
#define ST_STRIDE 72
#define SMEM_GEMM (128 * XS_STRIDE * 2 + 64 * WS_STRIDE * 2 + 128 * ST_STRIDE * 2)

__global__ void __launch_bounds__(256) gemm_fw_kernel(const float* __restrict__ X, int nN) {
    extern __shared__ __half smh[];
    __half* Xs = smh;                               // [128][136]
    __half* Ws = smh + 128 * XS_STRIDE;             // [64][136]
    __half* St = Ws + 64 * WS_STRIDE;               // [128][72]

    const int tid = threadIdx.x;
    const int wid = tid >> 5;
    const int lane = tid & 31;
    const int g = lane >> 2;
    const int tg = lane & 3;
    const int node0 = blockIdx.x * 128;
    const int wrow = wid * 16;

    const uint4* wsrc = (const uint4*)g_Wh;
    uint4 w0 = __ldg(wsrc + tid);
    uint4 w1 = __ldg(wsrc + 256 + tid);
    uint4 w2 = __ldg(wsrc + 512 + tid);
    uint4 w3 = __ldg(wsrc + 768 + tid);

    {
        const float4* X4 = (const float4*)X;
        #pragma unroll 4
        for (int i = tid; i < 4096; i += 256) {
            int row = i >> 5, q = i & 31;
            int gn = node0 + row;
            float4 v = (gn < nN) ? X4[(size_t)gn * 32 + q] : make_float4(0.f, 0.f, 0.f, 0.f);
            __half2 h0 = __floats2half2_rn(v.x, v.y);
            __half2 h1 = __floats2half2_rn(v.z, v.w);
            uint2 packed = make_uint2(*(uint32_t*)&h0, *(uint32_t*)&h1);
            *(uint2*)(Xs + row * XS_STRIDE + q * 4) = packed;
        }
    }

    for (int s = 0; s < NREL; s++) {
        {
            int i0 = tid,        n0 = i0 >> 4, q0 = i0 & 15;
            int i1 = 256 + tid,  n1 = i1 >> 4, q1 = i1 & 15;
            int i2 = 512 + tid,  n2 = i2 >> 4, q2 = i2 & 15;
            int i3 = 768 + tid,  n3 = i3 >> 4, q3 = i3 & 15;
            *(uint4*)(Ws + n0 * WS_STRIDE + q0 * 8) = w0;
            *(uint4*)(Ws + n1 * WS_STRIDE + q1 * 8) = w1;
            *(uint4*)(Ws + n2 * WS_STRIDE + q2 * 8) = w2;
            *(uint4*)(Ws + n3 * WS_STRIDE + q3 * 8) = w3;
        }
        if (s < NREL - 1) {
            const uint4* nx = wsrc + (s + 1) * 1024;
            w0 = __ldg(nx + tid);
            w1 = __ldg(nx + 256 + tid);
            w2 = __ldg(nx + 512 + tid);
            w3 = __ldg(nx + 768 + tid);
        }
        __syncthreads();

        float d[8][4];
        #pragma unroll
        for (int ni = 0; ni < 8; ni++)
            #pragma unroll
            for (int j = 0; j < 4; j++) d[ni][j] = 0.f;

        #pragma unroll
        for (int ks = 0; ks < 8; ks++) {
            const __half* ar = Xs + (wrow + g) * XS_STRIDE + ks * 16 + tg * 2;
            uint32_t a0 = *(const uint32_t*)(ar);
            uint32_t a1 = *(const uint32_t*)(ar + 8 * XS_STRIDE);
            uint32_t a2 = *(const uint32_t*)(ar + 8);
            uint32_t a3 = *(const uint32_t*)(ar + 8 * XS_STRIDE + 8);
            #pragma unroll
            for (int ni = 0; ni < 8; ni++) {
                const __half* br = Ws + (ni * 8 + g) * WS_STRIDE + ks * 16 + tg * 2;
                uint32_t b0 = *(const uint32_t*)(br);
                uint32_t b1 = *(const uint32_t*)(br + 8);
                mma_f16(d[ni], a0, a1, a2, a3, b0, b1);
            }
        }

        {
            __half* s0 = St + (wrow + g) * ST_STRIDE;
            __half* s1 = St + (wrow + 8 + g) * ST_STRIDE;
            #pragma unroll
            for (int ni = 0; ni < 8; ni++) {
                int c = ni * 8 + tg * 2;
                *(__half2*)(s0 + c) = __floats2half2_rn(d[ni][0], d[ni][1]);
                *(__half2*)(s1 + c) = __floats2half2_rn(d[ni][2], d[ni][3]);
            }
        }
        __syncthreads();
        {
            __half* fwbase = g_FWh + (size_t)s * nN * ODIM;
            #pragma unroll
            for (int i = tid; i < 1024; i += 256) {
                int r = i >> 3, q = i & 7;
                int gn = node0 + r;
                if (gn < nN) {
                    uint4 v = *(const uint4*)(St + r * ST_STRIDE + q * 8);
                    *(uint4*)(fwbase + (size_t)gn * ODIM + q * 8) = v;
                }
            }
        }
    }
}

// ---------------------------------------------------------------------------
// CSR build (round-7 design, correctness proven)
// ---------------------------------------------------------------------------
__global__ void zero_cnt_kernel(int nN) {
    int i = blockIdx.x * blockDim.x + threadIdx.x;
    if (i < nN) g_cnt[i] = 0;
}

__global__ void hist_kernel(const int* __restrict__ rows, int E) {
    int e = blockIdx.x * blockDim.x + threadIdx.x;
    if (e < E) atomicAdd(&g_cnt[__ldg(rows + e)], 1);
}

__global__ void __launch_bounds__(1024) scan_kernel(int nN) {
    __shared__ int ssum[1024];
    const int tid = threadIdx.x;
    const int chunk = (nN + 1023) / 1024;
    const int start = tid * chunk;
    const int end = min(start + chunk, nN);

    int sum = 0;
    for (int i = start; i < end; i++) sum += g_cnt[i];
    ssum[tid] = sum;
    __syncthreads();

    #pragma unroll
    for (int d = 1; d < 1024; d <<= 1) {
        int v = (tid >= d) ? ssum[tid - d] : 0;
        __syncthreads();
        ssum[tid] += v;
        __syncthreads();
    }
    int base = (tid == 0) ? 0 : ssum[tid - 1];

    for (int i = start; i < end; i++) {
        int c = g_cnt[i];
        g_off[i] = base;
        g_pos[i] = base;
        base += c;
    }
    if (tid == 1023) g_off[nN] = base;
}

__global__ void scatter_kernel(const int* __restrict__ rows, const int* __restrict__ cols,
                               const float* __restrict__ vals, int E) {
    int e = blockIdx.x * blockDim.x + threadIdx.x;
    if (e >= E) return;
    int r = __ldg(rows + e);
    int p = atomicAdd(&g_pos[r], 1);
    g_pairs[p] = make_uint2((uint32_t)__ldg(cols + e), __float_as_uint(__ldg(vals + e)));
}

// ---------------------------------------------------------------------------
// Kernel 2: deep-MLP pull + fused bias/ReLU. One warp per row.
// Per 32-edge chunk: ONE coalesced pair LDG, shfl-broadcast, fully-unrolled
// 32 independent FW gathers in flight (MLP~32). No atomics, no memset.
// ---------------------------------------------------------------------------
__global__ void __launch_bounds__(256) pull_kernel(float* __restrict__ out,
                                                   const float* __restrict__ bias, int nN) {
    int row = blockIdx.x * 8 + (threadIdx.x >> 5);
    if (row >= nN) return;
    const int lane = threadIdx.x & 31;
    const uint32_t FULL = 0xFFFFFFFFu;

    int i = g_off[row];
    const int end = g_off[row + 1];

    float a0 = 0.f, a1 = 0.f;

    // Full 32-edge chunks: fully unrolled -> 32 independent gathers in flight
    while (i + 32 <= end) {
        uint2 pr = __ldg(&g_pairs[i + lane]);
        #pragma unroll
        for (int j = 0; j < 32; j++) {
            int col = __shfl_sync(FULL, (int)pr.x, j);
            float v = __uint_as_float(__shfl_sync(FULL, (int)pr.y, j));
            uint32_t h = *(const uint32_t*)(g_FWh + (size_t)col * ODIM + lane * 2);
            float2 f = __half22float2(*(__half2*)&h);
            a0 = fmaf(v, f.x, a0);
            a1 = fmaf(v, f.y, a1);
        }
        i += 32;
    }
    // Tail (< 32 edges)
    {
        int m = end - i;
        if (m > 0) {
            uint2 pr = make_uint2(0u, 0u);
            if (lane < m) pr = __ldg(&g_pairs[i + lane]);
            #pragma unroll 4
            for (int j = 0; j < m; j++) {
                int col = __shfl_sync(FULL, (int)pr.x, j);
                float v = __uint_as_float(__shfl_sync(FULL, (int)pr.y, j));
                uint32_t h = *(const uint32_t*)(g_FWh + (size_t)col * ODIM + lane * 2);
                float2 f = __half22float2(*(__half2*)&h);
                a0 = fmaf(v, f.x, a0);
                a1 = fmaf(v, f.y, a1);
            }
        }
    }

    float2 bb = __ldg((const float2*)bias + lane);
    float2 o;
    o.x = fmaxf(a0 + bb.x, 0.f);
    o.y = fmaxf(a1 + bb.y, 0.f);
    *(float2*)(out + (size_t)row * ODIM + lane * 2) = o;
}

// ---------------------------------------------------------------------------
extern "C" void kernel_launch(void* const* d_in, const int* in_sizes, int n_in,
                              void* d_out, int out_size) {
    const float* X     = (const float*)d_in[0];   // [N, 128]
    const int*   rows  = (const int*)  d_in[1];   // [E]
    const int*   cols  = (const int*)  d_in[2];   // [E]
    const float* vals  = (const float*)d_in[3];   // [E]
    const float* bases = (const float*)d_in[4];   // [4, 128, 64]
    const float* comp  = (const float*)d_in[5];   // [8, 4]
    const float* bias  = (const float*)d_in[6];   // [64]
    float* out = (float*)d_out;                   // [N, 64]

    int nN = in_sizes[0] / FDIM;
    int E  = in_sizes[1];

    cudaFuncSetAttribute(gemm_fw_kernel, cudaFuncAttributeMaxDynamicSharedMemorySize, SMEM_GEMM);

    // CSR build
    zero_cnt_kernel<<<(nN + 255) / 256, 256>>>(nN);
    hist_kernel<<<(E + 255) / 256, 256>>>(rows, E);
    scan_kernel<<<1, 1024>>>(nN);
    scatter_kernel<<<(E + 255) / 256, 256>>>(rows, cols, vals, E);

    wcomb_kernel<<<(NREL * FDIM * ODIM + 255) / 256, 256>>>(bases, comp);

    int gblocks = (nN + 127) / 128;
    gemm_fw_kernel<<<gblocks, 256, SMEM_GEMM>>>(X, nN);

    pull_kernel<<<(nN + 7) / 8, 256>>>(out, bias, nN);
}

// round 12
// speedup vs baseline: 1.1800x; 1.1800x over previous
#include <cuda_runtime.h>
#include <cuda_fp16.h>
#include <cstdint>

// Problem constants: N=100000, S=8, B=4, F=128, O=64, E=3.2M
#define MAXN 100000
#define MAXE 3300000
#define FDIM 128
#define ODIM 64
#define NBAS 4
#define NREL 8

// Scratch (__device__ globals; no runtime alloc allowed)
__device__ __half g_FWh[(size_t)NREL * MAXN * ODIM];  // [8, N, 64] fp16 (102.4 MB)
__device__ __half g_Wh[NREL * ODIM * FDIM];           // [8][n=64][k=128] fp16
__device__ int    g_bin_cnt[NREL];
__device__ int    g_bin_cur[NREL];
__device__ int    g_rows_b[MAXE];                     // edges sorted by relation bin
__device__ int    g_cols_b[MAXE];
__device__ float  g_vals_b[MAXE];

// ---------------------------------------------------------------------------
__device__ __forceinline__ void mma_f16(float* d, uint32_t a0, uint32_t a1, uint32_t a2,
                                        uint32_t a3, uint32_t b0, uint32_t b1) {
    asm volatile(
        "mma.sync.aligned.m16n8k16.row.col.f32.f16.f16.f32 "
        "{%0,%1,%2,%3}, {%4,%5,%6,%7}, {%8,%9}, {%0,%1,%2,%3};"
        : "+f"(d[0]), "+f"(d[1]), "+f"(d[2]), "+f"(d[3])
        : "r"(a0), "r"(a1), "r"(a2), "r"(a3), "r"(b0), "r"(b1));
}

// ---------------------------------------------------------------------------
// Kernel 0: W[s][n][k] = fp16( sum_b comp[s,b] * Bases[b][k][n] )
// ---------------------------------------------------------------------------
__global__ void wcomb_kernel(const float* __restrict__ bases, const float* __restrict__ comp) {
    int idx = blockIdx.x * blockDim.x + threadIdx.x;
    if (idx >= NREL * FDIM * ODIM) return;
    int s = idx >> 13;
    int r = idx & 8191;
    int n = r >> 7;
    int k = r & 127;
    float acc = 0.f;
    #pragma unroll
    for (int b = 0; b < NBAS; b++)
        acc += __ldg(comp + s * NBAS + b) * __ldg(bases + b * FDIM * ODIM + k * ODIM + n);
    g_Wh[idx] = __float2half_rn(acc);
}

// ---------------------------------------------------------------------------
// Kernel 1: FW[s] = X @ W[s]^T via fp16 mma; staged epilogue; W reg-prefetch.
// X loads use __ldcs (evict-first stream) so FW writes stay L2-resident.
// ---------------------------------------------------------------------------
#define XS_STRIDE 136
#define WS_STRIDE 136
#define ST_STRIDE 72
#define SMEM_GEMM (128 * XS_STRIDE * 2 + 64 * WS_STRIDE * 2 + 128 * ST_STRIDE * 2)

__global__ void __launch_bounds__(256) gemm_fw_kernel(const float* __restrict__ X, int nN) {
    extern __shared__ __half smh[];
    __half* Xs = smh;                               // [128][136]
    __half* Ws = smh + 128 * XS_STRIDE;             // [64][136]
    __half* St = Ws + 64 * WS_STRIDE;               // [128][72]

    const int tid = threadIdx.x;
    const int wid = tid >> 5;
    const int lane = tid & 31;
    const int g = lane >> 2;
    const int tg = lane & 3;
    const int node0 = blockIdx.x * 128;
    const int wrow = wid * 16;

    const uint4* wsrc = (const uint4*)g_Wh;
    uint4 w0 = __ldg(wsrc + tid);
    uint4 w1 = __ldg(wsrc + 256 + tid);
    uint4 w2 = __ldg(wsrc + 512 + tid);
    uint4 w3 = __ldg(wsrc + 768 + tid);

    {
        const float4* X4 = (const float4*)X;
        #pragma unroll 4
        for (int i = tid; i < 4096; i += 256) {
            int row = i >> 5, q = i & 31;
            int gn = node0 + row;
            float4 v = (gn < nN) ? __ldcs(X4 + (size_t)gn * 32 + q) : make_float4(0.f, 0.f, 0.f, 0.f);
            __half2 h0 = __floats2half2_rn(v.x, v.y);
            __half2 h1 = __floats2half2_rn(v.z, v.w);
            uint2 packed = make_uint2(*(uint32_t*)&h0, *(uint32_t*)&h1);
            *(uint2*)(Xs + row * XS_STRIDE + q * 4) = packed;
        }
    }

    for (int s = 0; s < NREL; s++) {
        {
            int i0 = tid,        n0 = i0 >> 4, q0 = i0 & 15;
            int i1 = 256 + tid,  n1 = i1 >> 4, q1 = i1 & 15;
            int i2 = 512 + tid,  n2 = i2 >> 4, q2 = i2 & 15;
            int i3 = 768 + tid,  n3 = i3 >> 4, q3 = i3 & 15;
            *(uint4*)(Ws + n0 * WS_STRIDE + q0 * 8) = w0;
            *(uint4*)(Ws + n1 * WS_STRIDE + q1 * 8) = w1;
            *(uint4*)(Ws + n2 * WS_STRIDE + q2 * 8) = w2;
            *(uint4*)(Ws + n3 * WS_STRIDE + q3 * 8) = w3;
        }
        if (s < NREL - 1) {
            const uint4* nx = wsrc + (s + 1) * 1024;
            w0 = __ldg(nx + tid);
            w1 = __ldg(nx + 256 + tid);
            w2 = __ldg(nx + 512 + tid);
            w3 = __ldg(nx + 768 + tid);
        }
        __syncthreads();

        float d[8][4];
        #pragma unroll
        for (int ni = 0; ni < 8; ni++)
            #pragma unroll
            for (int j = 0; j < 4; j++) d[ni][j] = 0.f;

        #pragma unroll
        for (int ks = 0; ks < 8; ks++) {
            const __half* ar = Xs + (wrow + g) * XS_STRIDE + ks * 16 + tg * 2;
            uint32_t a0 = *(const uint32_t*)(ar);
            uint32_t a1 = *(const uint32_t*)(ar + 8 * XS_STRIDE);
            uint32_t a2 = *(const uint32_t*)(ar + 8);
            uint32_t a3 = *(const uint32_t*)(ar + 8 * XS_STRIDE + 8);
            #pragma unroll
            for (int ni = 0; ni < 8; ni++) {
                const __half* br = Ws + (ni * 8 + g) * WS_STRIDE + ks * 16 + tg * 2;
                uint32_t b0 = *(const uint32_t*)(br);
                uint32_t b1 = *(const uint32_t*)(br + 8);
                mma_f16(d[ni], a0, a1, a2, a3, b0, b1);
            }
        }

        {
            __half* s0 = St + (wrow + g) * ST_STRIDE;
            __half* s1 = St + (wrow + 8 + g) * ST_STRIDE;
            #pragma unroll
            for (int ni = 0; ni < 8; ni++) {
                int c = ni * 8 + tg * 2;
                *(__half2*)(s0 + c) = __floats2half2_rn(d[ni][0], d[ni][1]);
                *(__half2*)(s1 + c) = __floats2half2_rn(d[ni][2], d[ni][3]);
            }
        }
        __syncthreads();
        {
            __half* fwbase = g_FWh + (size_t)s * nN * ODIM;
            #pragma unroll
            for (int i = tid; i < 1024; i += 256) {
                int r = i >> 3, q = i & 7;
                int gn = node0 + r;
                if (gn < nN) {
                    uint4 v = *(const uint4*)(St + r * ST_STRIDE + q * 8);
                    *(uint4*)(fwbase + (size_t)gn * ODIM + q * 8) = v;
                }
            }
        }
    }
}

// ---------------------------------------------------------------------------
// Relation binning: counting sort into 8 bins (s = col / N)
// ---------------------------------------------------------------------------
__global__ void bin_zero_kernel() {
    if (threadIdx.x < NREL) g_bin_cnt[threadIdx.x] = 0;
}

__global__ void bin_count_kernel(const int* __restrict__ cols, int E, int nN) {
    __shared__ int scnt[NREL];
    if (threadIdx.x < NREL) scnt[threadIdx.x] = 0;
    __syncthreads();
    int e = blockIdx.x * blockDim.x + threadIdx.x;
    if (e < E) atomicAdd(&scnt[__ldg(cols + e) / nN], 1);
    __syncthreads();
    if (threadIdx.x < NREL) atomicAdd(&g_bin_cnt[threadIdx.x], scnt[threadIdx.x]);
}

__global__ void bin_scan_kernel() {
    if (threadIdx.x == 0) {
        int base = 0;
        #pragma unroll
        for (int s = 0; s < NREL; s++) {
            int c = g_bin_cnt[s];
            g_bin_cur[s] = base;
            base += c;
        }
    }
}

// 1024 edges/block; block-aggregated reservation (8 global atomics/block)
__global__ void __launch_bounds__(256) bin_scatter_kernel(
        const int* __restrict__ rows, const int* __restrict__ cols,
        const float* __restrict__ vals, int E, int nN) {
    __shared__ int scnt[NREL];
    __shared__ int sbase[NREL];
    const int tid = threadIdx.x;
    if (tid < NREL) scnt[tid] = 0;
    __syncthreads();

    int e0 = blockIdx.x * 1024 + tid;
    int mys[4], myr[4], myc[4], myrank[4];
    float myv[4];
    #pragma unroll
    for (int j = 0; j < 4; j++) {
        int e = e0 + j * 256;
        if (e < E) {
            int c = __ldg(cols + e);
            int s = c / nN;
            mys[j] = s; myc[j] = c;
            myr[j] = __ldg(rows + e);
            myv[j] = __ldg(vals + e);
            myrank[j] = atomicAdd(&scnt[s], 1);
        } else mys[j] = -1;
    }
    __syncthreads();
    if (tid < NREL) sbase[tid] = atomicAdd(&g_bin_cur[tid], scnt[tid]);
    __syncthreads();
    #pragma unroll
    for (int j = 0; j < 4; j++) {
        if (mys[j] >= 0) {
            int d = sbase[mys[j]] + myrank[j];
            g_rows_b[d] = myr[j];
            g_cols_b[d] = myc[j];
            g_vals_b[d] = myv[j];
        }
    }
}

// ---------------------------------------------------------------------------
// Kernel 2: SpMM push over relation-binned edges. 8 thr/edge, red.v4.f32.
// Bin order => active FW slice (12.8MB) is L2-resident; evict_last pins it.
// ---------------------------------------------------------------------------
__global__ void spmm_kernel(float* __restrict__ out, int E) {
    int t = blockIdx.x * blockDim.x + threadIdx.x;
    int e = t >> 3;
    if (e >= E) return;
    int l = t & 7;

    uint64_t pol_keep;
    asm("createpolicy.fractional.L2::evict_last.b64 %0, 1.0;" : "=l"(pol_keep));

    int c = __ldg(&g_cols_b[e]);
    int r = __ldg(&g_rows_b[e]);
    float v = __ldg(&g_vals_b[e]);

    const __half* src = g_FWh + (size_t)c * ODIM + l * 8;
    uint4 p;
    asm("ld.global.nc.L2::cache_hint.v4.b32 {%0,%1,%2,%3}, [%4], %5;"
        : "=r"(p.x), "=r"(p.y), "=r"(p.z), "=r"(p.w)
        : "l"(src), "l"(pol_keep));

    float2 f0 = __half22float2(*(__half2*)&p.x);
    float2 f1 = __half22float2(*(__half2*)&p.y);
    float2 f2 = __half22float2(*(__half2*)&p.z);
    float2 f3 = __half22float2(*(__half2*)&p.w);

    float* dst = out + (size_t)r * ODIM + l * 8;
    asm volatile("red.global.add.v4.f32 [%0], {%1,%2,%3,%4};"
                 :: "l"(dst), "f"(f0.x * v), "f"(f0.y * v), "f"(f1.x * v), "f"(f1.y * v) : "memory");
    asm volatile("red.global.add.v4.f32 [%0], {%1,%2,%3,%4};"
                 :: "l"(dst + 4), "f"(f2.x * v), "f"(f2.y * v), "f"(f3.x * v), "f"(f3.y * v) : "memory");
}

// ---------------------------------------------------------------------------
// Kernel 3: out = relu(out + bias)
// ---------------------------------------------------------------------------
__global__ void bias_relu_kernel(float* __restrict__ out, const float* __restrict__ bias, int nN) {
    int idx = blockIdx.x * blockDim.x + threadIdx.x;
    int total = nN * 16;
    if (idx >= total) return;
    float4 v = ((float4*)out)[idx];
    int og = idx & 15;
    float4 bb = __ldg((const float4*)bias + og);
    v.x = fmaxf(v.x + bb.x, 0.f);
    v.y = fmaxf(v.y + bb.y, 0.f);
    v.z = fmaxf(v.z + bb.z, 0.f);
    v.w = fmaxf(v.w + bb.w, 0.f);
    ((float4*)out)[idx] = v;
}

// ---------------------------------------------------------------------------
extern "C" void kernel_launch(void* const* d_in, const int* in_sizes, int n_in,
                              void* d_out, int out_size) {
    const float* X     = (const float*)d_in[0];   // [N, 128]
    const int*   rows  = (const int*)  d_in[1];   // [E]
    const int*   cols  = (const int*)  d_in[2];   // [E]
    const float* vals  = (const float*)d_in[3];   // [E]
    const float* bases = (const float*)d_in[4];   // [4, 128, 64]
    const float* comp  = (const float*)d_in[5];   // [8, 4]
    const float* bias  = (const float*)d_in[6];   // [64]
    float* out = (float*)d_out;                   // [N, 64]

    int nN = in_sizes[0] / FDIM;
    int E  = in_sizes[1];

    cudaFuncSetAttribute(gemm_fw_kernel, cudaFuncAttributeMaxDynamicSharedMemorySize, SMEM_GEMM);

    cudaMemsetAsync(out, 0, (size_t)nN * ODIM * sizeof(float));

    // Relation binning (counting sort, 8 bins)
    bin_zero_kernel<<<1, 32>>>();
    bin_count_kernel<<<(E + 255) / 256, 256>>>(cols, E, nN);
    bin_scan_kernel<<<1, 32>>>();
    bin_scatter_kernel<<<(E + 1023) / 1024, 256>>>(rows, cols, vals, E, nN);

    wcomb_kernel<<<(NREL * FDIM * ODIM + 255) / 256, 256>>>(bases, comp);

    int gblocks = (nN + 127) / 128;
    gemm_fw_kernel<<<gblocks, 256, SMEM_GEMM>>>(X, nN);

    long long spthreads = (long long)E * 8;
    spmm_kernel<<<(int)((spthreads + 255) / 256), 256>>>(out, E);

    bias_relu_kernel<<<(nN * 16 + 255) / 256, 256>>>(out, bias, nN);
}

// round 13
// speedup vs baseline: 1.2648x; 1.0718x over previous
#include <cuda_runtime.h>
#include <cuda_fp16.h>
#include <cstdint>

// Problem constants: N=100000, S=8, B=4, F=128, O=64, E=3.2M
#define MAXN 100000
#define FDIM 128
#define ODIM 64
#define NBAS 4
#define NREL 8

// Scratch (__device__ globals; no runtime alloc allowed)
__device__ __half g_FWh[(size_t)NREL * MAXN * ODIM];  // [8, N, 64] fp16 (102.4 MB)
__device__ __half g_Wh[NREL * ODIM * FDIM];           // [8][n=64][k=128] fp16

// ---------------------------------------------------------------------------
__device__ __forceinline__ void mma_f16(float* d, uint32_t a0, uint32_t a1, uint32_t a2,
                                        uint32_t a3, uint32_t b0, uint32_t b1) {
    asm volatile(
        "mma.sync.aligned.m16n8k16.row.col.f32.f16.f16.f32 "
        "{%0,%1,%2,%3}, {%4,%5,%6,%7}, {%8,%9}, {%0,%1,%2,%3};"
        : "+f"(d[0]), "+f"(d[1]), "+f"(d[2]), "+f"(d[3])
        : "r"(a0), "r"(a1), "r"(a2), "r"(a3), "r"(b0), "r"(b1));
}

// ---------------------------------------------------------------------------
// Kernel 0: W[s][n][k] = fp16( sum_b comp[s,b] * Bases[b][k][n] )
// ---------------------------------------------------------------------------
__global__ void wcomb_kernel(const float* __restrict__ bases, const float* __restrict__ comp) {
    int idx = blockIdx.x * blockDim.x + threadIdx.x;
    if (idx >= NREL * FDIM * ODIM) return;
    int s = idx >> 13;
    int r = idx & 8191;
    int n = r >> 7;
    int k = r & 127;
    float acc = 0.f;
    #pragma unroll
    for (int b = 0; b < NBAS; b++)
        acc += __ldg(comp + s * NBAS + b) * __ldg(bases + b * FDIM * ODIM + k * ODIM + n);
    g_Wh[idx] = __float2half_rn(acc);
}

// ---------------------------------------------------------------------------
// Kernel 1: FW[s] = X @ W[s]^T, fp16 mma.
// NEW: A-fragments extracted ONCE to registers (relation-invariant);
//      Xs smem aliased by double-buffered Ws after extraction;
//      warp-local stage+flush (no epilogue barrier); ONE sync per relation.
// smem: max( Xs[128][136]h = 34816 , Ws0+Ws1 = 2*17408 ) + St[128][72]h = 18432
//       = 53248 B.
// ---------------------------------------------------------------------------
#define XS_STRIDE 136
#define WS_STRIDE 136
#define WS_BYTES  (64 * WS_STRIDE * 2)      // 17408
#define ST_STRIDE 72
#define SMEM_GEMM (128 * XS_STRIDE * 2 + 128 * ST_STRIDE * 2)   // 34816 + 18432

__global__ void __launch_bounds__(256) gemm_fw_kernel(const float* __restrict__ X, int nN) {
    extern __shared__ char smb[];
    __half* Xs = (__half*)smb;                          // [128][136], dies after extract
    __half* Wbuf[2] = { (__half*)smb, (__half*)(smb + WS_BYTES) };  // alias Xs
    __half* St = (__half*)(smb + 128 * XS_STRIDE * 2);  // [128][72], per-warp slices

    const int tid = threadIdx.x;
    const int wid = tid >> 5;
    const int lane = tid & 31;
    const int g = lane >> 2;
    const int tg = lane & 3;
    const int node0 = blockIdx.x * 128;
    const int wrow = wid * 16;

    // Prefetch W_0 into registers (retires under X-tile load)
    const uint4* wsrc = (const uint4*)g_Wh;
    uint4 w0 = __ldg(wsrc + tid);
    uint4 w1 = __ldg(wsrc + 256 + tid);
    uint4 w2 = __ldg(wsrc + 512 + tid);
    uint4 w3 = __ldg(wsrc + 768 + tid);

    // Phase 1: X tile -> smem (fp16)
    {
        const float4* X4 = (const float4*)X;
        #pragma unroll 4
        for (int i = tid; i < 4096; i += 256) {
            int row = i >> 5, q = i & 31;
            int gn = node0 + row;
            float4 v = (gn < nN) ? __ldcs(X4 + (size_t)gn * 32 + q) : make_float4(0.f, 0.f, 0.f, 0.f);
            __half2 h0 = __floats2half2_rn(v.x, v.y);
            __half2 h1 = __floats2half2_rn(v.z, v.w);
            uint2 packed = make_uint2(*(uint32_t*)&h0, *(uint32_t*)&h1);
            *(uint2*)(Xs + row * XS_STRIDE + q * 4) = packed;
        }
    }
    __syncthreads();

    // Phase 2: extract ALL A-fragments to registers (relation-invariant)
    uint32_t a[8][4];
    #pragma unroll
    for (int ks = 0; ks < 8; ks++) {
        const __half* ar = Xs + (wrow + g) * XS_STRIDE + ks * 16 + tg * 2;
        a[ks][0] = *(const uint32_t*)(ar);
        a[ks][1] = *(const uint32_t*)(ar + 8 * XS_STRIDE);
        a[ks][2] = *(const uint32_t*)(ar + 8);
        a[ks][3] = *(const uint32_t*)(ar + 8 * XS_STRIDE + 8);
    }
    __syncthreads();   // extraction done everywhere before Ws aliases Xs

    // Seed Ws buffer 0 with W_0; prefetch W_1
    {
        __half* Wd = Wbuf[0];
        int n0 = tid >> 4,         q0 = tid & 15;
        int n1 = (256+tid) >> 4,   q1 = (256+tid) & 15;
        int n2 = (512+tid) >> 4,   q2 = (512+tid) & 15;
        int n3 = (768+tid) >> 4,   q3 = (768+tid) & 15;
        *(uint4*)(Wd + n0 * WS_STRIDE + q0 * 8) = w0;
        *(uint4*)(Wd + n1 * WS_STRIDE + q1 * 8) = w1;
        *(uint4*)(Wd + n2 * WS_STRIDE + q2 * 8) = w2;
        *(uint4*)(Wd + n3 * WS_STRIDE + q3 * 8) = w3;
        const uint4* nx = wsrc + 1024;
        w0 = __ldg(nx + tid);
        w1 = __ldg(nx + 256 + tid);
        w2 = __ldg(nx + 512 + tid);
        w3 = __ldg(nx + 768 + tid);
    }
    __syncthreads();   // Ws0 ready

    for (int s = 0; s < NREL; s++) {
        const __half* Wc = Wbuf[s & 1];

        float d[8][4];
        #pragma unroll
        for (int ni = 0; ni < 8; ni++)
            #pragma unroll
            for (int j = 0; j < 4; j++) d[ni][j] = 0.f;

        #pragma unroll
        for (int ks = 0; ks < 8; ks++) {
            #pragma unroll
            for (int ni = 0; ni < 8; ni++) {
                const __half* br = Wc + (ni * 8 + g) * WS_STRIDE + ks * 16 + tg * 2;
                uint32_t b0 = *(const uint32_t*)(br);
                uint32_t b1 = *(const uint32_t*)(br + 8);
                mma_f16(d[ni], a[ks][0], a[ks][1], a[ks][2], a[ks][3], b0, b1);
            }
        }

        // Store next relation's W into the other buffer; prefetch s+2
        if (s < NREL - 1) {
            __half* Wd = Wbuf[(s + 1) & 1];
            int n0 = tid >> 4,         q0 = tid & 15;
            int n1 = (256+tid) >> 4,   q1 = (256+tid) & 15;
            int n2 = (512+tid) >> 4,   q2 = (512+tid) & 15;
            int n3 = (768+tid) >> 4,   q3 = (768+tid) & 15;
            *(uint4*)(Wd + n0 * WS_STRIDE + q0 * 8) = w0;
            *(uint4*)(Wd + n1 * WS_STRIDE + q1 * 8) = w1;
            *(uint4*)(Wd + n2 * WS_STRIDE + q2 * 8) = w2;
            *(uint4*)(Wd + n3 * WS_STRIDE + q3 * 8) = w3;
            if (s < NREL - 2) {
                const uint4* nx = wsrc + (s + 2) * 1024;
                w0 = __ldg(nx + tid);
                w1 = __ldg(nx + 256 + tid);
                w2 = __ldg(nx + 512 + tid);
                w3 = __ldg(nx + 768 + tid);
            }
        }

        // Warp-local stage (conflict-free STS) + warp-local coalesced flush
        {
            __half* s0 = St + (wrow + g) * ST_STRIDE;
            __half* s1 = St + (wrow + 8 + g) * ST_STRIDE;
            #pragma unroll
            for (int ni = 0; ni < 8; ni++) {
                int c = ni * 8 + tg * 2;
                *(__half2*)(s0 + c) = __floats2half2_rn(d[ni][0], d[ni][1]);
                *(__half2*)(s1 + c) = __floats2half2_rn(d[ni][2], d[ni][3]);
            }
            __syncwarp();
            __half* fwbase = g_FWh + (size_t)s * nN * ODIM;
            #pragma unroll
            for (int j = 0; j < 4; j++) {
                int i = lane + j * 32;          // 0..127 within warp slab
                int r = i >> 3, q = i & 7;      // local row 0..15, 16B group
                int gn = node0 + wrow + r;
                if (gn < nN) {
                    uint4 v = *(const uint4*)(St + (wrow + r) * ST_STRIDE + q * 8);
                    *(uint4*)(fwbase + (size_t)gn * ODIM + q * 8) = v;
                }
            }
        }

        __syncthreads();   // W-store(s+1) visible; also orders Wc reuse
    }
}

// ---------------------------------------------------------------------------
// Kernel 2: SpMM push: out[rows[e]] += vals[e] * FW[cols[e]] (fp16 gather)
// 8 thr/edge, evict_last on FW gather. (r10 version = best measured)
// ---------------------------------------------------------------------------
__global__ void spmm_kernel(const int* __restrict__ rows, const int* __restrict__ cols,
                            const float* __restrict__ vals, float* __restrict__ out, int E) {
    int t = blockIdx.x * blockDim.x + threadIdx.x;
    int e = t >> 3;
    if (e >= E) return;
    int l = t & 7;

    uint64_t pol_keep;
    asm("createpolicy.fractional.L2::evict_last.b64 %0, 1.0;" : "=l"(pol_keep));

    int c = __ldg(cols + e);
    int r = __ldg(rows + e);
    float v = __ldg(vals + e);

    const __half* src = g_FWh + (size_t)c * ODIM + l * 8;
    uint4 p;
    asm("ld.global.nc.L2::cache_hint.v4.b32 {%0,%1,%2,%3}, [%4], %5;"
        : "=r"(p.x), "=r"(p.y), "=r"(p.z), "=r"(p.w)
        : "l"(src), "l"(pol_keep));

    float2 f0 = __half22float2(*(__half2*)&p.x);
    float2 f1 = __half22float2(*(__half2*)&p.y);
    float2 f2 = __half22float2(*(__half2*)&p.z);
    float2 f3 = __half22float2(*(__half2*)&p.w);

    float* dst = out + (size_t)r * ODIM + l * 8;
    asm volatile("red.global.add.v4.f32 [%0], {%1,%2,%3,%4};"
                 :: "l"(dst), "f"(f0.x * v), "f"(f0.y * v), "f"(f1.x * v), "f"(f1.y * v) : "memory");
    asm volatile("red.global.add.v4.f32 [%0], {%1,%2,%3,%4};"
                 :: "l"(dst + 4), "f"(f2.x * v), "f"(f2.y * v), "f"(f3.x * v), "f"(f3.y * v) : "memory");
}

// ---------------------------------------------------------------------------
// Kernel 3: out = relu(out + bias)
// ---------------------------------------------------------------------------
__global__ void bias_relu_kernel(float* __restrict__ out, const float* __restrict__ bias, int nN) {
    int idx = blockIdx.x * blockDim.x + threadIdx.x;
    int total = nN * 16;
    if (idx >= total) return;
    float4 v = ((float4*)out)[idx];
    int og = idx & 15;
    float4 bb = __ldg((const float4*)bias + og);
    v.x = fmaxf(v.x + bb.x, 0.f);
    v.y = fmaxf(v.y + bb.y, 0.f);
    v.z = fmaxf(v.z + bb.z, 0.f);
    v.w = fmaxf(v.w + bb.w, 0.f);
    ((float4*)out)[idx] = v;
}

// ---------------------------------------------------------------------------
extern "C" void kernel_launch(void* const* d_in, const int* in_sizes, int n_in,
                              void* d_out, int out_size) {
    const float* X     = (const float*)d_in[0];   // [N, 128]
    const int*   rows  = (const int*)  d_in[1];   // [E]
    const int*   cols  = (const int*)  d_in[2];   // [E]
    const float* vals  = (const float*)d_in[3];   // [E]
    const float* bases = (const float*)d_in[4];   // [4, 128, 64]
    const float* comp  = (const float*)d_in[5];   // [8, 4]
    const float* bias  = (const float*)d_in[6];   // [64]
    float* out = (float*)d_out;                   // [N, 64]

    int nN = in_sizes[0] / FDIM;
    int E  = in_sizes[1];

    cudaFuncSetAttribute(gemm_fw_kernel, cudaFuncAttributeMaxDynamicSharedMemorySize, SMEM_GEMM);

    cudaMemsetAsync(out, 0, (size_t)nN * ODIM * sizeof(float));

    wcomb_kernel<<<(NREL * FDIM * ODIM + 255) / 256, 256>>>(bases, comp);

    int gblocks = (nN + 127) / 128;
    gemm_fw_kernel<<<gblocks, 256, SMEM_GEMM>>>(X, nN);

    long long spthreads = (long long)E * 8;
    spmm_kernel<<<(int)((spthreads + 255) / 256), 256>>>(rows, cols, vals, out, E);

    bias_relu_kernel<<<(nN * 16 + 255) / 256, 256>>>(out, bias, nN);
}

// round 15
// speedup vs baseline: 1.3177x; 1.0418x over previous
#include <cuda_runtime.h>
#include <cuda_fp16.h>
#include <cstdint>

// Problem constants: N=100000, S=8, B=4, F=128, O=64, E=3.2M
#define MAXN 100000
#define FDIM 128
#define ODIM 64
#define NBAS 4
#define NREL 8

// Scratch (__device__ globals; no runtime alloc allowed)
__device__ __half g_FWh[(size_t)NREL * MAXN * ODIM];  // [8, N, 64] fp16 (102.4 MB)
__device__ __half g_Bh[NBAS * ODIM * FDIM];           // [4][n=64][k=128] fp16 (transposed bases)

// ---------------------------------------------------------------------------
__device__ __forceinline__ void mma_f16(float* d, uint32_t a0, uint32_t a1, uint32_t a2,
                                        uint32_t a3, uint32_t b0, uint32_t b1) {
    asm volatile(
        "mma.sync.aligned.m16n8k16.row.col.f32.f16.f16.f32 "
        "{%0,%1,%2,%3}, {%4,%5,%6,%7}, {%8,%9}, {%0,%1,%2,%3};"
        : "+f"(d[0]), "+f"(d[1]), "+f"(d[2]), "+f"(d[3])
        : "r"(a0), "r"(a1), "r"(a2), "r"(a3), "r"(b0), "r"(b1));
}

// ---------------------------------------------------------------------------
// Kernel 0: B~[b][n][k] = fp16( Bases[b][k][n] )   (transpose + cast only)
// ---------------------------------------------------------------------------
__global__ void bcomb_kernel(const float* __restrict__ bases) {
    int idx = blockIdx.x * blockDim.x + threadIdx.x;
    if (idx >= NBAS * FDIM * ODIM) return;
    int b = idx >> 13;
    int r = idx & 8191;
    int n = r >> 7;            // 0..63
    int k = r & 127;           // 0..127
    g_Bh[idx] = __float2half_rn(__ldg(bases + b * FDIM * ODIM + k * ODIM + n));
}

// ---------------------------------------------------------------------------
// Kernel 1: XB[b] = X @ B~[b]^T for 4 bases (HALF the mma count), then
// in-register combine FW[s] = sum_b comp[s,b]*XB[b] for all 8 relations.
// 512 threads (16 warps). Warp w: rows (w&7)*16, cols (w>>3)*32.
// Accums d[4][4][4] (64 regs). Zero block-syncs in the relation epilogue.
// smem: basis tiles 4*64*136*2 = 69632 (aliases Xs 34816) + St 16*16*40*2 =
//       20480  -> 90112 B, 1 block/SM, 16 warps/SM.
// ---------------------------------------------------------------------------
#define XS_STRIDE 136
#define BS_STRIDE 136
#define BS_BYTES  (64 * BS_STRIDE * 2)      // 17408 per basis
#define ST_STRIDE 40                        // halves (20 words, STS conflict-free)
#define SM_ST_OFF (4 * BS_BYTES)            // 69632
#define SMEM_GEMM (SM_ST_OFF + 16 * 16 * ST_STRIDE * 2)   // 90112

__global__ void __launch_bounds__(512, 1) gemm_fw_kernel(const float* __restrict__ X,
                                                         const float* __restrict__ comp,
                                                         int nN) {
    extern __shared__ char smb[];
    __half* Xs = (__half*)smb;                         // [128][136], dies after extract
    const int tid = threadIdx.x;
    const int wid = tid >> 5;
    const int lane = tid & 31;
    const int g = lane >> 2;
    const int tg = lane & 3;
    const int node0 = blockIdx.x * 128;
    const int wrow = (wid & 7) * 16;                   // warp's row base (0..112)
    const int wc = (wid >> 3) * 32;                    // warp's col base (0 or 32)

    // Phase 1: X tile -> smem fp16
    {
        const float4* X4 = (const float4*)X;
        #pragma unroll 2
        for (int i = tid; i < 4096; i += 512) {
            int row = i >> 5, q = i & 31;
            int gn = node0 + row;
            float4 v = (gn < nN) ? __ldcs(X4 + (size_t)gn * 32 + q) : make_float4(0.f, 0.f, 0.f, 0.f);
            __half2 h0 = __floats2half2_rn(v.x, v.y);
            __half2 h1 = __floats2half2_rn(v.z, v.w);
            uint2 packed = make_uint2(*(uint32_t*)&h0, *(uint32_t*)&h1);
            *(uint2*)(Xs + row * XS_STRIDE + q * 4) = packed;
        }
    }
    __syncthreads();

    // Phase 2: extract A-fragments (row-dependent only; held all kernel)
    uint32_t a[8][4];
    #pragma unroll
    for (int ks = 0; ks < 8; ks++) {
        const __half* ar = Xs + (wrow + g) * XS_STRIDE + ks * 16 + tg * 2;
        a[ks][0] = *(const uint32_t*)(ar);
        a[ks][1] = *(const uint32_t*)(ar + 8 * XS_STRIDE);
        a[ks][2] = *(const uint32_t*)(ar + 8);
        a[ks][3] = *(const uint32_t*)(ar + 8 * XS_STRIDE + 8);
    }
    __syncthreads();   // Xs dead; basis tiles may alias it now

    // Phase 3: load all 4 basis tiles [64][128]h into smem (4096 uint4)
    {
        const uint4* src = (const uint4*)g_Bh;
        #pragma unroll
        for (int i = tid; i < 4096; i += 512) {
            int b = i >> 10, j = i & 1023;
            int n = j >> 4, q = j & 15;
            *(uint4*)(smb + b * BS_BYTES + (n * BS_STRIDE + q * 8) * 2) = __ldg(src + i);
        }
    }
    __syncthreads();

    // Phase 4: 4 basis GEMMs into register accumulators
    float d[NBAS][4][4];
    #pragma unroll
    for (int b = 0; b < NBAS; b++)
        #pragma unroll
        for (int ni = 0; ni < 4; ni++)
            #pragma unroll
            for (int j = 0; j < 4; j++) d[b][ni][j] = 0.f;

    #pragma unroll
    for (int b = 0; b < NBAS; b++) {
        const __half* Bs = (const __half*)(smb + b * BS_BYTES);
        #pragma unroll
        for (int ks = 0; ks < 8; ks++) {
            #pragma unroll
            for (int ni = 0; ni < 4; ni++) {
                const __half* br = Bs + (wc + ni * 8 + g) * BS_STRIDE + ks * 16 + tg * 2;
                uint32_t b0 = *(const uint32_t*)(br);
                uint32_t b1 = *(const uint32_t*)(br + 8);
                mma_f16(d[b][ni], a[ks][0], a[ks][1], a[ks][2], a[ks][3], b0, b1);
            }
        }
    }

    // Phase 5: per-relation combine + warp-local stage + coalesced flush
    __half* Stw = (__half*)(smb + SM_ST_OFF) + wid * 16 * ST_STRIDE;
    for (int s = 0; s < NREL; s++) {
        float c0 = __ldg(comp + s * NBAS + 0);
        float c1 = __ldg(comp + s * NBAS + 1);
        float c2 = __ldg(comp + s * NBAS + 2);
        float c3 = __ldg(comp + s * NBAS + 3);

        __half* s0 = Stw + g * ST_STRIDE;
        __half* s1 = Stw + (8 + g) * ST_STRIDE;
        #pragma unroll
        for (int ni = 0; ni < 4; ni++) {
            float f0 = c0*d[0][ni][0] + c1*d[1][ni][0] + c2*d[2][ni][0] + c3*d[3][ni][0];
            float f1 = c0*d[0][ni][1] + c1*d[1][ni][1] + c2*d[2][ni][1] + c3*d[3][ni][1];
            float f2 = c0*d[0][ni][2] + c1*d[1][ni][2] + c2*d[2][ni][2] + c3*d[3][ni][2];
            float f3 = c0*d[0][ni][3] + c1*d[1][ni][3] + c2*d[2][ni][3] + c3*d[3][ni][3];
            int c = ni * 8 + tg * 2;
            *(__half2*)(s0 + c) = __floats2half2_rn(f0, f1);
            *(__half2*)(s1 + c) = __floats2half2_rn(f2, f3);
        }
        __syncwarp();

        // Flush warp's 16 rows x 32 cols: 64 chunks of 16B, 2 iters
        __half* fwbase = g_FWh + (size_t)s * nN * ODIM;
        #pragma unroll
        for (int j = 0; j < 2; j++) {
            int idx = lane + j * 32;
            int r = idx >> 2, q = idx & 3;
            int gn = node0 + wrow + r;
            if (gn < nN) {
                uint4 v = *(const uint4*)(Stw + r * ST_STRIDE + q * 8);
                *(uint4*)(fwbase + (size_t)gn * ODIM + wc + q * 8) = v;
            }
        }
        __syncwarp();   // St reuse next relation
    }
}

// ---------------------------------------------------------------------------
// Kernel 2: SpMM push: out[rows[e]] += vals[e] * FW[cols[e]] (fp16 gather)
// 8 thr/edge, evict_last on FW gather. (best measured variant)
// ---------------------------------------------------------------------------
__global__ void spmm_kernel(const int* __restrict__ rows, const int* __restrict__ cols,
                            const float* __restrict__ vals, float* __restrict__ out, int E) {
    int t = blockIdx.x * blockDim.x + threadIdx.x;
    int e = t >> 3;
    if (e >= E) return;
    int l = t & 7;

    uint64_t pol_keep;
    asm("createpolicy.fractional.L2::evict_last.b64 %0, 1.0;" : "=l"(pol_keep));

    int c = __ldg(cols + e);
    int r = __ldg(rows + e);
    float v = __ldg(vals + e);

    const __half* src = g_FWh + (size_t)c * ODIM + l * 8;
    uint4 p;
    asm("ld.global.nc.L2::cache_hint.v4.b32 {%0,%1,%2,%3}, [%4], %5;"
        : "=r"(p.x), "=r"(p.y), "=r"(p.z), "=r"(p.w)
        : "l"(src), "l"(pol_keep));

    float2 f0 = __half22float2(*(__half2*)&p.x);
    float2 f1 = __half22float2(*(__half2*)&p.y);
    float2 f2 = __half22float2(*(__half2*)&p.z);
    float2 f3 = __half22float2(*(__half2*)&p.w);

    float* dst = out + (size_t)r * ODIM + l * 8;
    asm volatile("red.global.add.v4.f32 [%0], {%1,%2,%3,%4};"
                 :: "l"(dst), "f"(f0.x * v), "f"(f0.y * v), "f"(f1.x * v), "f"(f1.y * v) : "memory");
    asm volatile("red.global.add.v4.f32 [%0], {%1,%2,%3,%4};"
                 :: "l"(dst + 4), "f"(f2.x * v), "f"(f2.y * v), "f"(f3.x * v), "f"(f3.y * v) : "memory");
}

// ---------------------------------------------------------------------------
// Kernel 3: out = relu(out + bias)
// ---------------------------------------------------------------------------
__global__ void bias_relu_kernel(float* __restrict__ out, const float* __restrict__ bias, int nN) {
    int idx = blockIdx.x * blockDim.x + threadIdx.x;
    int total = nN * 16;
    if (idx >= total) return;
    float4 v = ((float4*)out)[idx];
    int og = idx & 15;
    float4 bb = __ldg((const float4*)bias + og);
    v.x = fmaxf(v.x + bb.x, 0.f);
    v.y = fmaxf(v.y + bb.y, 0.f);
    v.z = fmaxf(v.z + bb.z, 0.f);
    v.w = fmaxf(v.w + bb.w, 0.f);
    ((float4*)out)[idx] = v;
}

// ---------------------------------------------------------------------------
extern "C" void kernel_launch(void* const* d_in, const int* in_sizes, int n_in,
                              void* d_out, int out_size) {
    const float* X     = (const float*)d_in[0];   // [N, 128]
    const int*   rows  = (const int*)  d_in[1];   // [E]
    const int*   cols  = (const int*)  d_in[2];   // [E]
    const float* vals  = (const float*)d_in[3];   // [E]
    const float* bases = (const float*)d_in[4];   // [4, 128, 64]
    const float* comp  = (const float*)d_in[5];   // [8, 4]
    const float* bias  = (const float*)d_in[6];   // [64]
    float* out = (float*)d_out;                   // [N, 64]

    int nN = in_sizes[0] / FDIM;
    int E  = in_sizes[1];

    cudaFuncSetAttribute(gemm_fw_kernel, cudaFuncAttributeMaxDynamicSharedMemorySize, SMEM_GEMM);

    cudaMemsetAsync(out, 0, (size_t)nN * ODIM * sizeof(float));

    bcomb_kernel<<<(NBAS * FDIM * ODIM + 255) / 256, 256>>>(bases);

    int gblocks = (nN + 127) / 128;
    gemm_fw_kernel<<<gblocks, 512, SMEM_GEMM>>>(X, comp, nN);

    long long spthreads = (long long)E * 8;
    spmm_kernel<<<(int)((spthreads + 255) / 256), 256>>>(rows, cols, vals, out, E);

    bias_relu_kernel<<<(nN * 16 + 255) / 256, 256>>>(out, bias, nN);
}